// round 1
// baseline (speedup 1.0000x reference)
#include <cuda_runtime.h>

#define BB 16
#define TT 512
#define VV 64
#define C0 16
#define HH 64
#define BT (BB*TT)      // 8192
#define VH (VV*HH)      // 4096
#define TC 256

// ---------------- scratch (device globals; no allocation allowed) ----------
__device__ float g_adjT[BB*VV*VV];                 // adj_norm transposed: [b][w][v]
__device__ float g_z1[(size_t)BT*VV*HH];           // 134 MB
__device__ float g_z2[(size_t)BT*VV*HH];           // 134 MB
__device__ float g_psum1[HH*BT];
__device__ float g_psq1[HH*BT];
__device__ float g_psum2[HH*BT];
__device__ float g_psq2[HH*BT];
__device__ float g_a1[HH], g_c1[HH], g_a2[HH], g_c2[HH];
__device__ float g_S[BB*VH], g_E0[BB*VH], g_E1[BB*VH];
__device__ float g_y[BB*TC];

// ---------------- K0: degree-normalized adjacency (transposed) -------------
__global__ void k_adj(const float* __restrict__ adj) {
    int b = blockIdx.x;
    int tid = threadIdx.x;
    __shared__ float dis[VV];
    const float* A = adj + b*VV*VV;
    if (tid < VV) {
        float s = 0.f;
        #pragma unroll 8
        for (int w = 0; w < VV; w++) s += A[tid*VV + w];
        dis[tid] = rsqrtf(s + 1e-6f);
    }
    __syncthreads();
    // adjT[w][v] = dis[v] * A[v][w] * dis[w]
    for (int idx = tid; idx < VV*VV; idx += 256) {
        int w = idx >> 6, v = idx & 63;
        g_adjT[b*VV*VV + idx] = dis[v] * A[v*VV + w] * dis[w];
    }
}

// ---------------- K1: z1 = (A @ X) @ W1 + b1, + per-block BN partials ------
__global__ void __launch_bounds__(256) k_layer1(const float* __restrict__ x,
                                                const float* __restrict__ w1,
                                                const float* __restrict__ b1) {
    int bt = blockIdx.x;          // 0..8191
    int b  = bt >> 9;
    int tid = threadIdx.x;
    __shared__ float At[VV*VV];   // 16KB; reused later as z-tile for stats
    __shared__ float Xs[VV*C0];   // 4KB
    __shared__ float W1s[C0*HH];  // 4KB
    __shared__ float tmpT[C0*VV]; // 4KB

    const float* Ag = g_adjT + b*VV*VV;
    for (int i = tid; i < VV*VV; i += 256) At[i] = Ag[i];
    const float* Xg = x + (size_t)bt*VV*C0;
    for (int i = tid; i < VV*C0; i += 256) Xs[i] = Xg[i];
    for (int i = tid; i < C0*HH; i += 256) W1s[i] = w1[i];
    __syncthreads();

    // step 1: tmp[v][c] = sum_w At[w][v] * X[w][c]; thread -> (vq, c)
    {
        int vq = (tid >> 4) * 4, c = tid & 15;
        float a0=0.f, a1=0.f, a2=0.f, a3=0.f;
        #pragma unroll 8
        for (int w = 0; w < VV; w++) {
            float4 av = *(const float4*)&At[w*VV + vq];
            float xv = Xs[w*C0 + c];
            a0 += av.x*xv; a1 += av.y*xv; a2 += av.z*xv; a3 += av.w*xv;
        }
        *(float4*)&tmpT[c*VV + vq] = make_float4(a0,a1,a2,a3);
    }
    __syncthreads();

    // step 2: z[v][h] = b1[h] + sum_c tmpT[c][v] * W1[c][h]; thread -> (vq, hq)
    int vq = (tid >> 4) * 4, hq = (tid & 15) * 4;
    float4 bb = *(const float4*)&b1[hq];
    float acc[4][4];
    #pragma unroll
    for (int i = 0; i < 4; i++) { acc[i][0]=bb.x; acc[i][1]=bb.y; acc[i][2]=bb.z; acc[i][3]=bb.w; }
    #pragma unroll
    for (int c = 0; c < C0; c++) {
        float4 t4 = *(const float4*)&tmpT[c*VV + vq];
        float4 w4 = *(const float4*)&W1s[c*HH + hq];
        const float tv[4] = {t4.x,t4.y,t4.z,t4.w};
        const float wv[4] = {w4.x,w4.y,w4.z,w4.w};
        #pragma unroll
        for (int i = 0; i < 4; i++)
            #pragma unroll
            for (int j = 0; j < 4; j++)
                acc[i][j] += tv[i]*wv[j];
    }
    __syncthreads();              // done reading At: reuse as z tile
    float* zs = At;
    float* zg = g_z1 + (size_t)bt*VV*HH;
    #pragma unroll
    for (int i = 0; i < 4; i++) {
        float4 r = make_float4(acc[i][0],acc[i][1],acc[i][2],acc[i][3]);
        *(float4*)&zs[(vq+i)*HH + hq] = r;
        *(float4*)&zg[(vq+i)*HH + hq] = r;
    }
    __syncthreads();
    if (tid < HH) {               // fixed-order column reduce (deterministic)
        float s = 0.f, q = 0.f;
        #pragma unroll 8
        for (int v = 0; v < VV; v++) { float z = zs[v*HH + tid]; s += z; q += z*z; }
        g_psum1[tid*BT + bt] = s;
        g_psq1[tid*BT + bt]  = q;
    }
}

// ---------------- K2: finalize BN affine (a = g*rsqrt(var+eps), c = be-mean*a)
__global__ void k_stats(int layer, const float* __restrict__ g, const float* __restrict__ be) {
    int h = blockIdx.x, tid = threadIdx.x;
    const float* ps = layer ? g_psum2 : g_psum1;
    const float* pq = layer ? g_psq2  : g_psq1;
    __shared__ float ss[256], sq[256];
    float s = 0.f, q = 0.f;
    for (int i = tid; i < BT; i += 256) { s += ps[h*BT + i]; q += pq[h*BT + i]; }
    ss[tid] = s; sq[tid] = q;
    __syncthreads();
    for (int st = 128; st > 0; st >>= 1) {
        if (tid < st) { ss[tid] += ss[tid+st]; sq[tid] += sq[tid+st]; }
        __syncthreads();
    }
    if (tid == 0) {
        const float N = (float)(BT*VV);
        float mean = ss[0] / N;
        float var  = sq[0] / N - mean*mean;
        float av = g[h] * rsqrtf(var + 1e-5f);
        if (layer) { g_a2[h] = av; g_c2[h] = be[h] - mean*av; }
        else       { g_a1[h] = av; g_c1[h] = be[h] - mean*av; }
    }
}

// ---------------- K3: x1 = relu(BN(z1)); z2 = (A @ x1) @ W2 + b2, + partials
extern __shared__ float smem3[];
__global__ void __launch_bounds__(256) k_layer2(const float* __restrict__ w2,
                                                const float* __restrict__ b2) {
    int bt = blockIdx.x, b = bt >> 9, tid = threadIdx.x;
    float* At   = smem3;              // 4096 floats
    float* X1s  = smem3 + 4096;       // 4096 (reused as z2 tile)
    float* tmpT = smem3 + 8192;       // 4096
    float* W2s  = smem3 + 12288;      // 4096

    const float* Ag = g_adjT + b*VV*VV;
    for (int i = tid; i < VV*VV; i += 256) At[i] = Ag[i];
    for (int i = tid; i < HH*HH; i += 256) W2s[i] = w2[i];
    const float* zg1 = g_z1 + (size_t)bt*VV*HH;
    for (int i = tid; i < VV*HH; i += 256) {
        int h = i & 63;
        X1s[i] = fmaxf(fmaf(zg1[i], g_a1[h], g_c1[h]), 0.f);
    }
    __syncthreads();

    int vq = (tid >> 4) * 4, hq = (tid & 15) * 4;
    // step 1: tmp[v][h] = sum_w At[w][v] * X1[w][h]
    float acc[4][4] = {};
    #pragma unroll 4
    for (int w = 0; w < VV; w++) {
        float4 a4 = *(const float4*)&At[w*VV + vq];
        float4 x4 = *(const float4*)&X1s[w*HH + hq];
        const float av[4] = {a4.x,a4.y,a4.z,a4.w};
        const float xv[4] = {x4.x,x4.y,x4.z,x4.w};
        #pragma unroll
        for (int i = 0; i < 4; i++)
            #pragma unroll
            for (int j = 0; j < 4; j++)
                acc[i][j] += av[i]*xv[j];
    }
    #pragma unroll
    for (int j = 0; j < 4; j++)
        *(float4*)&tmpT[(hq+j)*VV + vq] =
            make_float4(acc[0][j],acc[1][j],acc[2][j],acc[3][j]);
    __syncthreads();

    // step 2: z2[v][o] = b2[o] + sum_h tmpT[h][v] * W2[h][o]
    float4 bb = *(const float4*)&b2[hq];
    float acc2[4][4];
    #pragma unroll
    for (int i = 0; i < 4; i++) { acc2[i][0]=bb.x; acc2[i][1]=bb.y; acc2[i][2]=bb.z; acc2[i][3]=bb.w; }
    #pragma unroll 4
    for (int h2 = 0; h2 < HH; h2++) {
        float4 t4 = *(const float4*)&tmpT[h2*VV + vq];
        float4 w4 = *(const float4*)&W2s[h2*HH + hq];
        const float tv[4] = {t4.x,t4.y,t4.z,t4.w};
        const float wv[4] = {w4.x,w4.y,w4.z,w4.w};
        #pragma unroll
        for (int i = 0; i < 4; i++)
            #pragma unroll
            for (int j = 0; j < 4; j++)
                acc2[i][j] += tv[i]*wv[j];
    }
    float* zs = X1s;                  // safe: step2 does not read X1s
    float* zg2 = g_z2 + (size_t)bt*VV*HH;
    #pragma unroll
    for (int i = 0; i < 4; i++) {
        float4 r = make_float4(acc2[i][0],acc2[i][1],acc2[i][2],acc2[i][3]);
        *(float4*)&zs[(vq+i)*HH + hq] = r;
        *(float4*)&zg2[(vq+i)*HH + hq] = r;
    }
    __syncthreads();
    if (tid < HH) {
        float s = 0.f, q = 0.f;
        #pragma unroll 8
        for (int v = 0; v < VV; v++) { float z = zs[v*HH + tid]; s += z; q += z*z; }
        g_psum2[tid*BT + bt] = s;
        g_psq2[tid*BT + bt]  = q;
    }
}

// ---------------- K4: x = relu(BN(z1)) + relu(BN(z2)); reduce over T -------
__global__ void __launch_bounds__(256) k_reduce_t() {
    int bv = blockIdx.x;              // B*V
    int b = bv >> 6, v = bv & 63;
    int tid = threadIdx.x;
    int h = tid & 63, ph = tid >> 6;  // 4 t-phases
    float a1 = g_a1[h], c1 = g_c1[h], a2 = g_a2[h], c2 = g_c2[h];
    size_t base = ((size_t)b*TT*VV + v)*HH + h;
    float s = 0.f, e0 = 0.f, e1 = 0.f;
    for (int t = ph; t < TT; t += 4) {
        size_t idx = base + (size_t)t*VV*HH;
        float z1v = g_z1[idx], z2v = g_z2[idx];
        float xv = fmaxf(fmaf(z1v, a1, c1), 0.f) + fmaxf(fmaf(z2v, a2, c2), 0.f);
        s += xv;
        if (t == 0)     e0 = xv;
        if (t == TT-1)  e1 = xv;
    }
    __shared__ float sred[4][64], se0[64], se1[64];
    sred[ph][h] = s;
    if (ph == 0) se0[h] = e0;
    if (ph == 3) se1[h] = e1;
    __syncthreads();
    if (tid < 64) {
        float tot = sred[0][tid] + sred[1][tid] + sred[2][tid] + sred[3][tid];
        int o = b*VH + v*HH + tid;
        g_S[o] = tot; g_E0[o] = se0[tid]; g_E1[o] = se1[tid];
    }
}

// ---------------- K5: collapsed conv+mean: y[b][o] ------------------------
__global__ void __launch_bounds__(256) k_pool(const float* __restrict__ tw,
                                              const float* __restrict__ tb) {
    int o = blockIdx.x;               // 256
    int tid = threadIdx.x;
    float acc[BB];
    #pragma unroll
    for (int b = 0; b < BB; b++) acc[b] = 0.f;
    const float* two = tw + (size_t)o*VH*3;
    for (int i = tid; i < VH; i += 256) {
        float t0 = two[i*3+0], t1 = two[i*3+1], t2 = two[i*3+2];
        float ts = t0 + t1 + t2;
        #pragma unroll
        for (int b = 0; b < BB; b++) {
            int ix = b*VH + i;
            acc[b] += ts*g_S[ix] - t0*g_E1[ix] - t2*g_E0[ix];
        }
    }
    __shared__ float red[256];
    float tbv = tb[o];
    #pragma unroll 1
    for (int b = 0; b < BB; b++) {
        red[tid] = acc[b];
        __syncthreads();
        for (int st = 128; st > 0; st >>= 1) {
            if (tid < st) red[tid] += red[tid+st];
            __syncthreads();
        }
        if (tid == 0) g_y[b*TC + o] = red[0]*(1.f/TT) + tbv;
        __syncthreads();
    }
}

// ---------------- K6: FC head ---------------------------------------------
__global__ void __launch_bounds__(256) k_fc(const float* __restrict__ f1w,
                                            const float* __restrict__ f1b,
                                            const float* __restrict__ f2w,
                                            const float* __restrict__ f2b,
                                            float* __restrict__ out) {
    __shared__ float ys[BB*TC];
    __shared__ float hs[BB*128];
    int tid = threadIdx.x;
    for (int i = tid; i < BB*TC; i += 256) ys[i] = g_y[i];
    __syncthreads();
    int b = tid >> 4, jq = (tid & 15) * 8;
    float acc[8];
    #pragma unroll
    for (int j = 0; j < 8; j++) acc[j] = f1b[jq+j];
    for (int o = 0; o < TC; o++) {
        float yv = ys[b*TC + o];
        const float* w = f1w + o*128 + jq;
        #pragma unroll
        for (int j = 0; j < 8; j++) acc[j] += yv * w[j];
    }
    #pragma unroll
    for (int j = 0; j < 8; j++) hs[b*128 + jq + j] = fmaxf(acc[j], 0.f);
    __syncthreads();
    if (tid < BB*10) {
        int bb = tid / 10, n = tid % 10;
        float s = f2b[n];
        #pragma unroll 8
        for (int j = 0; j < 128; j++) s += hs[bb*128 + j] * f2w[j*10 + n];
        out[tid] = s;
    }
}

// ---------------- launch ----------------------------------------------------
extern "C" void kernel_launch(void* const* d_in, const int* in_sizes, int n_in,
                              void* d_out, int out_size) {
    const float* x    = (const float*)d_in[0];
    const float* adj  = (const float*)d_in[1];
    const float* w1   = (const float*)d_in[2];
    const float* b1   = (const float*)d_in[3];
    const float* g1   = (const float*)d_in[4];
    const float* be1  = (const float*)d_in[5];
    const float* w2   = (const float*)d_in[6];
    const float* b2   = (const float*)d_in[7];
    const float* g2   = (const float*)d_in[8];
    const float* be2  = (const float*)d_in[9];
    const float* tw   = (const float*)d_in[10];
    const float* tb   = (const float*)d_in[11];
    const float* f1w  = (const float*)d_in[12];
    const float* f1b  = (const float*)d_in[13];
    const float* f2w  = (const float*)d_in[14];
    const float* f2b  = (const float*)d_in[15];
    float* out = (float*)d_out;

    // k_layer2 needs 64 KB dynamic smem (> default 48 KB)
    cudaFuncSetAttribute(k_layer2, cudaFuncAttributeMaxDynamicSharedMemorySize, 64*1024);

    k_adj<<<BB, 256>>>(adj);
    k_layer1<<<BT, 256>>>(x, w1, b1);
    k_stats<<<HH, 256>>>(0, g1, be1);
    k_layer2<<<BT, 256, 64*1024>>>(w2, b2);
    k_stats<<<HH, 256>>>(1, g2, be2);
    k_reduce_t<<<BB*VV, 256>>>();
    k_pool<<<TC, 256>>>(tw, tb);
    k_fc<<<1, 256>>>(f1w, f1b, f2w, f2b, out);
}

// round 2
// speedup vs baseline: 1.0008x; 1.0008x over previous
#include <cuda_runtime.h>

#define BB 16
#define TT 512
#define VV 64
#define C0 16
#define HH 64
#define BT (BB*TT)      // 8192
#define VH (VV*HH)      // 4096
#define TC 256

// ---------------- scratch (device globals; no allocation allowed) ----------
__device__ float g_adjT[BB*VV*VV];                 // adj_norm transposed: [b][w][v]
__device__ float g_z1[(size_t)BT*VV*HH];           // 134 MB
__device__ float g_z2[(size_t)BT*VV*HH];           // 134 MB
__device__ float g_psum1[HH*BT];
__device__ float g_psq1[HH*BT];
__device__ float g_psum2[HH*BT];
__device__ float g_psq2[HH*BT];
__device__ float g_a1[HH], g_c1[HH], g_a2[HH], g_c2[HH];
__device__ float g_S[BB*VH], g_E0[BB*VH], g_E1[BB*VH];
__device__ float g_y[BB*TC];

// ---------------- K0: degree-normalized adjacency (transposed) -------------
__global__ void k_adj(const float* __restrict__ adj) {
    int b = blockIdx.x;
    int tid = threadIdx.x;
    __shared__ float dis[VV];
    const float* A = adj + b*VV*VV;
    if (tid < VV) {
        float s = 0.f;
        #pragma unroll 8
        for (int w = 0; w < VV; w++) s += A[tid*VV + w];
        dis[tid] = rsqrtf(s + 1e-6f);
    }
    __syncthreads();
    // adjT[w][v] = dis[v] * A[v][w] * dis[w]
    for (int idx = tid; idx < VV*VV; idx += 256) {
        int w = idx >> 6, v = idx & 63;
        g_adjT[b*VV*VV + idx] = dis[v] * A[v*VV + w] * dis[w];
    }
}

// ---------------- K1: z1 = (A @ X) @ W1 + b1, + per-block BN partials ------
__global__ void __launch_bounds__(256) k_layer1(const float* __restrict__ x,
                                                const float* __restrict__ w1,
                                                const float* __restrict__ b1) {
    int bt = blockIdx.x;          // 0..8191
    int b  = bt >> 9;
    int tid = threadIdx.x;
    __shared__ float At[VV*VV];   // 16KB; reused later as z-tile for stats
    __shared__ float Xs[VV*C0];   // 4KB
    __shared__ float W1s[C0*HH];  // 4KB
    __shared__ float tmpT[C0*VV]; // 4KB

    const float* Ag = g_adjT + b*VV*VV;
    for (int i = tid; i < VV*VV; i += 256) At[i] = Ag[i];
    const float* Xg = x + (size_t)bt*VV*C0;
    for (int i = tid; i < VV*C0; i += 256) Xs[i] = Xg[i];
    for (int i = tid; i < C0*HH; i += 256) W1s[i] = w1[i];
    __syncthreads();

    // step 1: tmp[v][c] = sum_w At[w][v] * X[w][c]; thread -> (vq, c)
    {
        int vq = (tid >> 4) * 4, c = tid & 15;
        float a0=0.f, a1=0.f, a2=0.f, a3=0.f;
        #pragma unroll 8
        for (int w = 0; w < VV; w++) {
            float4 av = *(const float4*)&At[w*VV + vq];
            float xv = Xs[w*C0 + c];
            a0 += av.x*xv; a1 += av.y*xv; a2 += av.z*xv; a3 += av.w*xv;
        }
        *(float4*)&tmpT[c*VV + vq] = make_float4(a0,a1,a2,a3);
    }
    __syncthreads();

    // step 2: z[v][h] = b1[h] + sum_c tmpT[c][v] * W1[c][h]; thread -> (vq, hq)
    int vq = (tid >> 4) * 4, hq = (tid & 15) * 4;
    float4 bb = *(const float4*)&b1[hq];
    float acc[4][4];
    #pragma unroll
    for (int i = 0; i < 4; i++) { acc[i][0]=bb.x; acc[i][1]=bb.y; acc[i][2]=bb.z; acc[i][3]=bb.w; }
    #pragma unroll
    for (int c = 0; c < C0; c++) {
        float4 t4 = *(const float4*)&tmpT[c*VV + vq];
        float4 w4 = *(const float4*)&W1s[c*HH + hq];
        const float tv[4] = {t4.x,t4.y,t4.z,t4.w};
        const float wv[4] = {w4.x,w4.y,w4.z,w4.w};
        #pragma unroll
        for (int i = 0; i < 4; i++)
            #pragma unroll
            for (int j = 0; j < 4; j++)
                acc[i][j] += tv[i]*wv[j];
    }
    __syncthreads();              // done reading At: reuse as z tile
    float* zs = At;
    float* zg = g_z1 + (size_t)bt*VV*HH;
    #pragma unroll
    for (int i = 0; i < 4; i++) {
        float4 r = make_float4(acc[i][0],acc[i][1],acc[i][2],acc[i][3]);
        *(float4*)&zs[(vq+i)*HH + hq] = r;
        *(float4*)&zg[(vq+i)*HH + hq] = r;
    }
    __syncthreads();
    if (tid < HH) {               // fixed-order column reduce (deterministic)
        float s = 0.f, q = 0.f;
        #pragma unroll 8
        for (int v = 0; v < VV; v++) { float z = zs[v*HH + tid]; s += z; q += z*z; }
        g_psum1[tid*BT + bt] = s;
        g_psq1[tid*BT + bt]  = q;
    }
}

// ---------------- K2: finalize BN affine (a = g*rsqrt(var+eps), c = be-mean*a)
__global__ void k_stats(int layer, const float* __restrict__ g, const float* __restrict__ be) {
    int h = blockIdx.x, tid = threadIdx.x;
    const float* ps = layer ? g_psum2 : g_psum1;
    const float* pq = layer ? g_psq2  : g_psq1;
    __shared__ float ss[256], sq[256];
    float s = 0.f, q = 0.f;
    for (int i = tid; i < BT; i += 256) { s += ps[h*BT + i]; q += pq[h*BT + i]; }
    ss[tid] = s; sq[tid] = q;
    __syncthreads();
    for (int st = 128; st > 0; st >>= 1) {
        if (tid < st) { ss[tid] += ss[tid+st]; sq[tid] += sq[tid+st]; }
        __syncthreads();
    }
    if (tid == 0) {
        const float N = (float)(BT*VV);
        float mean = ss[0] / N;
        float var  = sq[0] / N - mean*mean;
        float av = g[h] * rsqrtf(var + 1e-5f);
        if (layer) { g_a2[h] = av; g_c2[h] = be[h] - mean*av; }
        else       { g_a1[h] = av; g_c1[h] = be[h] - mean*av; }
    }
}

// ---------------- K3: x1 = relu(BN(z1)); z2 = (A @ x1) @ W2 + b2, + partials
extern __shared__ float smem3[];
__global__ void __launch_bounds__(256) k_layer2(const float* __restrict__ w2,
                                                const float* __restrict__ b2) {
    int bt = blockIdx.x, b = bt >> 9, tid = threadIdx.x;
    float* At   = smem3;              // 4096 floats
    float* X1s  = smem3 + 4096;       // 4096 (reused as z2 tile)
    float* tmpT = smem3 + 8192;       // 4096
    float* W2s  = smem3 + 12288;      // 4096

    const float* Ag = g_adjT + b*VV*VV;
    for (int i = tid; i < VV*VV; i += 256) At[i] = Ag[i];
    for (int i = tid; i < HH*HH; i += 256) W2s[i] = w2[i];
    const float* zg1 = g_z1 + (size_t)bt*VV*HH;
    for (int i = tid; i < VV*HH; i += 256) {
        int h = i & 63;
        X1s[i] = fmaxf(fmaf(zg1[i], g_a1[h], g_c1[h]), 0.f);
    }
    __syncthreads();

    int vq = (tid >> 4) * 4, hq = (tid & 15) * 4;
    // step 1: tmp[v][h] = sum_w At[w][v] * X1[w][h]
    float acc[4][4] = {};
    #pragma unroll 4
    for (int w = 0; w < VV; w++) {
        float4 a4 = *(const float4*)&At[w*VV + vq];
        float4 x4 = *(const float4*)&X1s[w*HH + hq];
        const float av[4] = {a4.x,a4.y,a4.z,a4.w};
        const float xv[4] = {x4.x,x4.y,x4.z,x4.w};
        #pragma unroll
        for (int i = 0; i < 4; i++)
            #pragma unroll
            for (int j = 0; j < 4; j++)
                acc[i][j] += av[i]*xv[j];
    }
    #pragma unroll
    for (int j = 0; j < 4; j++)
        *(float4*)&tmpT[(hq+j)*VV + vq] =
            make_float4(acc[0][j],acc[1][j],acc[2][j],acc[3][j]);
    __syncthreads();

    // step 2: z2[v][o] = b2[o] + sum_h tmpT[h][v] * W2[h][o]
    float4 bb = *(const float4*)&b2[hq];
    float acc2[4][4];
    #pragma unroll
    for (int i = 0; i < 4; i++) { acc2[i][0]=bb.x; acc2[i][1]=bb.y; acc2[i][2]=bb.z; acc2[i][3]=bb.w; }
    #pragma unroll 4
    for (int h2 = 0; h2 < HH; h2++) {
        float4 t4 = *(const float4*)&tmpT[h2*VV + vq];
        float4 w4 = *(const float4*)&W2s[h2*HH + hq];
        const float tv[4] = {t4.x,t4.y,t4.z,t4.w};
        const float wv[4] = {w4.x,w4.y,w4.z,w4.w};
        #pragma unroll
        for (int i = 0; i < 4; i++)
            #pragma unroll
            for (int j = 0; j < 4; j++)
                acc2[i][j] += tv[i]*wv[j];
    }
    float* zs = X1s;                  // safe: step2 does not read X1s
    float* zg2 = g_z2 + (size_t)bt*VV*HH;
    #pragma unroll
    for (int i = 0; i < 4; i++) {
        float4 r = make_float4(acc2[i][0],acc2[i][1],acc2[i][2],acc2[i][3]);
        *(float4*)&zs[(vq+i)*HH + hq] = r;
        *(float4*)&zg2[(vq+i)*HH + hq] = r;
    }
    __syncthreads();
    if (tid < HH) {
        float s = 0.f, q = 0.f;
        #pragma unroll 8
        for (int v = 0; v < VV; v++) { float z = zs[v*HH + tid]; s += z; q += z*z; }
        g_psum2[tid*BT + bt] = s;
        g_psq2[tid*BT + bt]  = q;
    }
}

// ---------------- K4: x = relu(BN(z1)) + relu(BN(z2)); reduce over T -------
__global__ void __launch_bounds__(256) k_reduce_t() {
    int bv = blockIdx.x;              // B*V
    int b = bv >> 6, v = bv & 63;
    int tid = threadIdx.x;
    int h = tid & 63, ph = tid >> 6;  // 4 t-phases
    float a1 = g_a1[h], c1 = g_c1[h], a2 = g_a2[h], c2 = g_c2[h];
    size_t base = ((size_t)b*TT*VV + v)*HH + h;
    float s = 0.f, e0 = 0.f, e1 = 0.f;
    for (int t = ph; t < TT; t += 4) {
        size_t idx = base + (size_t)t*VV*HH;
        float z1v = g_z1[idx], z2v = g_z2[idx];
        float xv = fmaxf(fmaf(z1v, a1, c1), 0.f) + fmaxf(fmaf(z2v, a2, c2), 0.f);
        s += xv;
        if (t == 0)     e0 = xv;
        if (t == TT-1)  e1 = xv;
    }
    __shared__ float sred[4][64], se0[64], se1[64];
    sred[ph][h] = s;
    if (ph == 0) se0[h] = e0;
    if (ph == 3) se1[h] = e1;
    __syncthreads();
    if (tid < 64) {
        float tot = sred[0][tid] + sred[1][tid] + sred[2][tid] + sred[3][tid];
        int o = b*VH + v*HH + tid;
        g_S[o] = tot; g_E0[o] = se0[tid]; g_E1[o] = se1[tid];
    }
}

// ---------------- K5: collapsed conv+mean: y[b][o] ------------------------
__global__ void __launch_bounds__(256) k_pool(const float* __restrict__ tw,
                                              const float* __restrict__ tb) {
    int o = blockIdx.x;               // 256
    int tid = threadIdx.x;
    float acc[BB];
    #pragma unroll
    for (int b = 0; b < BB; b++) acc[b] = 0.f;
    const float* two = tw + (size_t)o*VH*3;
    for (int i = tid; i < VH; i += 256) {
        float t0 = two[i*3+0], t1 = two[i*3+1], t2 = two[i*3+2];
        float ts = t0 + t1 + t2;
        #pragma unroll
        for (int b = 0; b < BB; b++) {
            int ix = b*VH + i;
            acc[b] += ts*g_S[ix] - t0*g_E1[ix] - t2*g_E0[ix];
        }
    }
    __shared__ float red[256];
    float tbv = tb[o];
    #pragma unroll 1
    for (int b = 0; b < BB; b++) {
        red[tid] = acc[b];
        __syncthreads();
        for (int st = 128; st > 0; st >>= 1) {
            if (tid < st) red[tid] += red[tid+st];
            __syncthreads();
        }
        if (tid == 0) g_y[b*TC + o] = red[0]*(1.f/TT) + tbv;
        __syncthreads();
    }
}

// ---------------- K6: FC head ---------------------------------------------
__global__ void __launch_bounds__(256) k_fc(const float* __restrict__ f1w,
                                            const float* __restrict__ f1b,
                                            const float* __restrict__ f2w,
                                            const float* __restrict__ f2b,
                                            float* __restrict__ out) {
    __shared__ float ys[BB*TC];
    __shared__ float hs[BB*128];
    int tid = threadIdx.x;
    for (int i = tid; i < BB*TC; i += 256) ys[i] = g_y[i];
    __syncthreads();
    int b = tid >> 4, jq = (tid & 15) * 8;
    float acc[8];
    #pragma unroll
    for (int j = 0; j < 8; j++) acc[j] = f1b[jq+j];
    for (int o = 0; o < TC; o++) {
        float yv = ys[b*TC + o];
        const float* w = f1w + o*128 + jq;
        #pragma unroll
        for (int j = 0; j < 8; j++) acc[j] += yv * w[j];
    }
    #pragma unroll
    for (int j = 0; j < 8; j++) hs[b*128 + jq + j] = fmaxf(acc[j], 0.f);
    __syncthreads();
    if (tid < BB*10) {
        int bb = tid / 10, n = tid % 10;
        float s = f2b[n];
        #pragma unroll 8
        for (int j = 0; j < 128; j++) s += hs[bb*128 + j] * f2w[j*10 + n];
        out[tid] = s;
    }
}

// ---------------- launch ----------------------------------------------------
extern "C" void kernel_launch(void* const* d_in, const int* in_sizes, int n_in,
                              void* d_out, int out_size) {
    const float* x    = (const float*)d_in[0];
    const float* adj  = (const float*)d_in[1];
    const float* w1   = (const float*)d_in[2];
    const float* b1   = (const float*)d_in[3];
    const float* g1   = (const float*)d_in[4];
    const float* be1  = (const float*)d_in[5];
    const float* w2   = (const float*)d_in[6];
    const float* b2   = (const float*)d_in[7];
    const float* g2   = (const float*)d_in[8];
    const float* be2  = (const float*)d_in[9];
    const float* tw   = (const float*)d_in[10];
    const float* tb   = (const float*)d_in[11];
    const float* f1w  = (const float*)d_in[12];
    const float* f1b  = (const float*)d_in[13];
    const float* f2w  = (const float*)d_in[14];
    const float* f2b  = (const float*)d_in[15];
    float* out = (float*)d_out;

    // k_layer2 needs 64 KB dynamic smem (> default 48 KB)
    cudaFuncSetAttribute(k_layer2, cudaFuncAttributeMaxDynamicSharedMemorySize, 64*1024);

    k_adj<<<BB, 256>>>(adj);
    k_layer1<<<BT, 256>>>(x, w1, b1);
    k_stats<<<HH, 256>>>(0, g1, be1);
    k_layer2<<<BT, 256, 64*1024>>>(w2, b2);
    k_stats<<<HH, 256>>>(1, g2, be2);
    k_reduce_t<<<BB*VV, 256>>>();
    k_pool<<<TC, 256>>>(tw, tb);
    k_fc<<<1, 256>>>(f1w, f1b, f2w, f2b, out);
}

// round 3
// speedup vs baseline: 1.3929x; 1.3918x over previous
#include <cuda_runtime.h>

typedef unsigned long long ull;

#define BB 16
#define TT 512
#define VV 64
#define C0 16
#define HH 64
#define BT (BB*TT)      // 8192
#define VH (VV*HH)      // 4096
#define TC 256
#define NCHUNK 64       // TT/8 : 8 t's per CTA

// ---------------- scratch (device globals; no allocation allowed) ----------
__device__ float g_adjT[BB*VV*VV];
__device__ float g_z1[(size_t)BT*VH];           // 134 MB
__device__ float g_z2[(size_t)BT*VH];           // 134 MB
__device__ float g_psum1[HH*BT];
__device__ float g_psq1[HH*BT];
__device__ float g_psum2[HH*BT];
__device__ float g_psq2[HH*BT];
__device__ float g_a1[HH], g_c1[HH], g_a2[HH], g_c2[HH];
__device__ float g_S1p[(size_t)BB*NCHUNK*VH];   // per-chunk partial sums of x1 (16.7MB)
__device__ float g_E0x1[BB*VH], g_E1x1[BB*VH];  // x1 at t=0 / t=TT-1
__device__ float g_S[BB*VH], g_E0[BB*VH], g_E1[BB*VH];
__device__ float g_y[BB*TC];

// ---------------- packed f32x2 helpers -------------------------------------
__device__ __forceinline__ void ffma2(ull& d, ull a, ull b) {
    asm("fma.rn.f32x2 %0, %1, %2, %0;" : "+l"(d) : "l"(a), "l"(b));
}
__device__ __forceinline__ ull dup2(float x) {
    ull r; asm("mov.b64 %0, {%1, %1};" : "=l"(r) : "f"(x)); return r;
}
__device__ __forceinline__ float2 ull2f2(ull u) {
    float2 f; asm("mov.b64 {%0, %1}, %2;" : "=f"(f.x), "=f"(f.y) : "l"(u)); return f;
}

// ---------------- K0: degree-normalized adjacency (transposed) -------------
__global__ void k_adj(const float* __restrict__ adj) {
    int b = blockIdx.x;
    int tid = threadIdx.x;
    __shared__ float dis[VV];
    const float* A = adj + b*VV*VV;
    if (tid < VV) {
        float s = 0.f;
        #pragma unroll 8
        for (int w = 0; w < VV; w++) s += A[tid*VV + w];
        dis[tid] = rsqrtf(s + 1e-6f);
    }
    __syncthreads();
    for (int idx = tid; idx < VV*VV; idx += 256) {
        int w = idx >> 6, v = idx & 63;
        g_adjT[b*VV*VV + idx] = dis[v] * A[v*VV + w] * dis[w];
    }
}

// ---------------- K1: z1 = (A @ X) @ W1 + b1 (8 t's/CTA, FFMA2) ------------
__global__ void __launch_bounds__(256) k_layer1(const float* __restrict__ x,
                                                const float* __restrict__ w1,
                                                const float* __restrict__ b1) {
    int blk = blockIdx.x;                 // 1024
    int b = blk >> 6, chunk = blk & 63;
    int tid = threadIdx.x;
    extern __shared__ float sm1[];
    float* At   = sm1;                    // 4096
    float* W1s  = sm1 + 4096;             // 1024
    float* Xp   = sm1 + 5120;             // 2048 : [w=64][n=32]  n = p*16+c
    float* tmpT = sm1 + 7168;             // 2048 : [n=32][v=64]
    float* red  = sm1 + 9216;             // 4096 : redS 2048 + redQ 2048

    const float* Ag = g_adjT + b*4096;
    for (int i = tid; i < 4096; i += 256) At[i] = Ag[i];
    for (int i = tid; i < 1024; i += 256) W1s[i] = w1[i];

    int mg = tid >> 3, og = tid & 7, o8 = og*8;
    ulonglong2 bA = *(const ulonglong2*)&b1[o8];
    ulonglong2 bB = *(const ulonglong2*)&b1[o8+4];
    int vg = tid & 15, ng = tid >> 4;
    int v4 = vg*4, n2 = ng*2;
    int p2 = mg >> 4, vv4 = (mg*4) & 63;
    __syncthreads();

    for (int pair = 0; pair < 4; pair++) {
        int t0 = chunk*8 + pair*2;
        size_t xbase = (size_t)(b*TT + t0) * (VV*C0);
        // build Xp: two tiles of [64][16]
        #pragma unroll
        for (int k = 0; k < 2; k++) {
            int i4 = 4*tid + k*1024;         // 0..2047
            int p = i4 >> 10, idx = i4 & 1023;
            int w = idx >> 4, c4 = idx & 15;
            *(float4*)&Xp[w*32 + p*16 + c4] = *(const float4*)&x[xbase + i4];
        }
        __syncthreads();

        // stage1: tmpT[n][v] = sum_w At[w][v] * Xp[w][n]
        {
            ull acc[4];
            acc[0]=acc[1]=acc[2]=acc[3]=0ULL;
            #pragma unroll 8
            for (int w = 0; w < 64; w++) {
                float4 a4 = *(const float4*)&At[w*64 + v4];
                ull xv = *(const ull*)&Xp[w*32 + n2];
                ffma2(acc[0], dup2(a4.x), xv);
                ffma2(acc[1], dup2(a4.y), xv);
                ffma2(acc[2], dup2(a4.z), xv);
                ffma2(acc[3], dup2(a4.w), xv);
            }
            float2 r0=ull2f2(acc[0]), r1=ull2f2(acc[1]), r2=ull2f2(acc[2]), r3=ull2f2(acc[3]);
            *(float4*)&tmpT[n2*64 + v4]     = make_float4(r0.x,r1.x,r2.x,r3.x);
            *(float4*)&tmpT[(n2+1)*64 + v4] = make_float4(r0.y,r1.y,r2.y,r3.y);
        }
        __syncthreads();

        // stage2: z1[m=(p,v)][o] = b1[o] + sum_c tmpT[p*16+c][v] * W1[c][o]
        {
            ull acc2[4][4];
            #pragma unroll
            for (int m = 0; m < 4; m++) {
                acc2[m][0]=bA.x; acc2[m][1]=bA.y; acc2[m][2]=bB.x; acc2[m][3]=bB.y;
            }
            #pragma unroll
            for (int c = 0; c < 16; c++) {
                float4 t4 = *(const float4*)&tmpT[(p2*16 + c)*64 + vv4];
                ulonglong2 wA = *(const ulonglong2*)&W1s[c*64 + o8];
                ulonglong2 wB = *(const ulonglong2*)&W1s[c*64 + o8 + 4];
                ull wv[4] = {wA.x, wA.y, wB.x, wB.y};
                ull dd[4] = {dup2(t4.x), dup2(t4.y), dup2(t4.z), dup2(t4.w)};
                #pragma unroll
                for (int m = 0; m < 4; m++)
                    #pragma unroll
                    for (int q = 0; q < 4; q++) ffma2(acc2[m][q], dd[m], wv[q]);
            }
            size_t zb = (size_t)(b*TT + t0)*VH + (size_t)p2*VH + (size_t)vv4*64 + o8;
            #pragma unroll
            for (int m = 0; m < 4; m++) {
                *(ulonglong2*)&g_z1[zb + m*64]     = make_ulonglong2(acc2[m][0], acc2[m][1]);
                *(ulonglong2*)&g_z1[zb + m*64 + 4] = make_ulonglong2(acc2[m][2], acc2[m][3]);
            }
            // BN partials (fixed order -> deterministic)
            float s[8], qv[8];
            #pragma unroll
            for (int j = 0; j < 8; j++) { s[j]=0.f; qv[j]=0.f; }
            #pragma unroll
            for (int m = 0; m < 4; m++)
                #pragma unroll
                for (int q = 0; q < 4; q++) {
                    float2 f = ull2f2(acc2[m][q]);
                    s[2*q]   += f.x; qv[2*q]   += f.x*f.x;
                    s[2*q+1] += f.y; qv[2*q+1] += f.y*f.y;
                }
            float* redS = red; float* redQ = red + 2048;
            #pragma unroll
            for (int j = 0; j < 8; j++) { redS[mg*64 + o8 + j] = s[j]; redQ[mg*64 + o8 + j] = qv[j]; }
            __syncthreads();
            if (tid < 128) {
                int pp = tid >> 6, h = tid & 63;
                float ss = 0.f, qq = 0.f;
                #pragma unroll 4
                for (int g = 0; g < 16; g++) { ss += redS[(pp*16+g)*64 + h]; qq += redQ[(pp*16+g)*64 + h]; }
                int bt = b*TT + t0 + pp;
                g_psum1[h*BT + bt] = ss; g_psq1[h*BT + bt] = qq;
            }
        }
    }
}

// ---------------- K2: finalize BN affine ------------------------------------
__global__ void k_stats(int layer, const float* __restrict__ g, const float* __restrict__ be) {
    int h = blockIdx.x, tid = threadIdx.x;
    const float* ps = layer ? g_psum2 : g_psum1;
    const float* pq = layer ? g_psq2  : g_psq1;
    __shared__ float ss[256], sq[256];
    float s = 0.f, q = 0.f;
    for (int i = tid; i < BT; i += 256) { s += ps[h*BT + i]; q += pq[h*BT + i]; }
    ss[tid] = s; sq[tid] = q;
    __syncthreads();
    for (int st = 128; st > 0; st >>= 1) {
        if (tid < st) { ss[tid] += ss[tid+st]; sq[tid] += sq[tid+st]; }
        __syncthreads();
    }
    if (tid == 0) {
        const float N = (float)(BT*VV);
        float mean = ss[0] / N;
        float var  = sq[0] / N - mean*mean;
        float av = g[h] * rsqrtf(var + 1e-5f);
        if (layer) { g_a2[h] = av; g_c2[h] = be[h] - mean*av; }
        else       { g_a1[h] = av; g_c1[h] = be[h] - mean*av; }
    }
}

// ---------------- K3: x1=relu(BN(z1)); z2=(A@x1)@W2+b2; S1 partials --------
__global__ void __launch_bounds__(256, 2) k_layer2(const float* __restrict__ w2,
                                                   const float* __restrict__ b2) {
    int blk = blockIdx.x;                 // 1024
    int b = blk >> 6, chunk = blk & 63;
    int tid = threadIdx.x;
    extern __shared__ float sm2[];
    float* At   = sm2;                    // 4096
    float* W2s  = sm2 + 4096;             // 4096
    float* Xp   = sm2 + 8192;             // 8192 : [w=64][n=128]  n = p*64+h
    float* tmpT = sm2 + 16384;            // 8192 : [n=128][v=64] (reused as red)
    float* S1a  = sm2 + 24576;            // 4096
    // total 28672 floats = 112 KB

    const float* Ag = g_adjT + b*4096;
    for (int i = tid; i < 4096; i += 256) At[i] = Ag[i];
    for (int i = tid; i < 4096; i += 256) W2s[i] = w2[i];
    #pragma unroll
    for (int k = 0; k < 4; k++) *(float4*)&S1a[4*tid + k*1024] = make_float4(0.f,0.f,0.f,0.f);

    int h4b = (4*tid) & 63;
    float4 A1 = *(const float4*)&g_a1[h4b];
    float4 C1 = *(const float4*)&g_c1[h4b];
    int mg = tid >> 3, og = tid & 7, o8 = og*8;
    ulonglong2 bA = *(const ulonglong2*)&b2[o8];
    ulonglong2 bB = *(const ulonglong2*)&b2[o8+4];
    int vg = tid & 15, ng = tid >> 4;
    int v4 = vg*4, n8 = ng*8;
    int p2 = mg >> 4, vv4 = (mg*4) & 63;
    __syncthreads();

    for (int pair = 0; pair < 4; pair++) {
        int t0 = chunk*8 + pair*2;
        size_t zbase = (size_t)(b*TT + t0) * VH;
        bool isE0 = (chunk == 0 && pair == 0);
        bool isE1 = (chunk == 63 && pair == 3);
        const float* z0 = g_z1 + zbase;

        // build X1 pair (relu+affine), accumulate S1
        #pragma unroll
        for (int k = 0; k < 4; k++) {
            int i4 = 4*tid + k*1024;          // 0..4095
            float4 u0 = *(const float4*)&z0[i4];
            float4 u1 = *(const float4*)&z0[VH + i4];
            float4 x0, x1;
            x0.x = fmaxf(fmaf(u0.x, A1.x, C1.x), 0.f);
            x0.y = fmaxf(fmaf(u0.y, A1.y, C1.y), 0.f);
            x0.z = fmaxf(fmaf(u0.z, A1.z, C1.z), 0.f);
            x0.w = fmaxf(fmaf(u0.w, A1.w, C1.w), 0.f);
            x1.x = fmaxf(fmaf(u1.x, A1.x, C1.x), 0.f);
            x1.y = fmaxf(fmaf(u1.y, A1.y, C1.y), 0.f);
            x1.z = fmaxf(fmaf(u1.z, A1.z, C1.z), 0.f);
            x1.w = fmaxf(fmaf(u1.w, A1.w, C1.w), 0.f);
            int w = i4 >> 6, hh = i4 & 63;
            *(float4*)&Xp[w*128 + hh]      = x0;
            *(float4*)&Xp[w*128 + 64 + hh] = x1;
            float4 sv = *(float4*)&S1a[i4];
            sv.x += x0.x + x1.x; sv.y += x0.y + x1.y;
            sv.z += x0.z + x1.z; sv.w += x0.w + x1.w;
            *(float4*)&S1a[i4] = sv;
            if (isE0) *(float4*)&g_E0x1[b*VH + i4] = x0;
            if (isE1) *(float4*)&g_E1x1[b*VH + i4] = x1;
        }
        __syncthreads();

        // stage1: tmpT[n][v] = sum_w At[w][v] * Xp[w][n]
        {
            ull acc[4][4];
            #pragma unroll
            for (int m = 0; m < 4; m++)
                #pragma unroll
                for (int q = 0; q < 4; q++) acc[m][q] = 0ULL;
            #pragma unroll 4
            for (int w = 0; w < 64; w++) {
                float4 a4 = *(const float4*)&At[w*64 + v4];
                ulonglong2 xA = *(const ulonglong2*)&Xp[w*128 + n8];
                ulonglong2 xB = *(const ulonglong2*)&Xp[w*128 + n8 + 4];
                ull xv[4] = {xA.x, xA.y, xB.x, xB.y};
                ull dd[4] = {dup2(a4.x), dup2(a4.y), dup2(a4.z), dup2(a4.w)};
                #pragma unroll
                for (int m = 0; m < 4; m++)
                    #pragma unroll
                    for (int q = 0; q < 4; q++) ffma2(acc[m][q], dd[m], xv[q]);
            }
            #pragma unroll
            for (int q = 0; q < 4; q++) {
                float2 r0=ull2f2(acc[0][q]), r1=ull2f2(acc[1][q]),
                       r2=ull2f2(acc[2][q]), r3=ull2f2(acc[3][q]);
                *(float4*)&tmpT[(n8+2*q)*64   + v4] = make_float4(r0.x,r1.x,r2.x,r3.x);
                *(float4*)&tmpT[(n8+2*q+1)*64 + v4] = make_float4(r0.y,r1.y,r2.y,r3.y);
            }
        }
        __syncthreads();

        // stage2: z2[m=(p,v)][o] = b2[o] + sum_h tmpT[p*64+h][v] * W2[h][o]
        {
            ull acc2[4][4];
            #pragma unroll
            for (int m = 0; m < 4; m++) {
                acc2[m][0]=bA.x; acc2[m][1]=bA.y; acc2[m][2]=bB.x; acc2[m][3]=bB.y;
            }
            #pragma unroll 4
            for (int h2 = 0; h2 < 64; h2++) {
                float4 t4 = *(const float4*)&tmpT[(p2*64 + h2)*64 + vv4];
                ulonglong2 wA = *(const ulonglong2*)&W2s[h2*64 + o8];
                ulonglong2 wB = *(const ulonglong2*)&W2s[h2*64 + o8 + 4];
                ull wv[4] = {wA.x, wA.y, wB.x, wB.y};
                ull dd[4] = {dup2(t4.x), dup2(t4.y), dup2(t4.z), dup2(t4.w)};
                #pragma unroll
                for (int m = 0; m < 4; m++)
                    #pragma unroll
                    for (int q = 0; q < 4; q++) ffma2(acc2[m][q], dd[m], wv[q]);
            }
            size_t zb = zbase + (size_t)p2*VH + (size_t)vv4*64 + o8;
            #pragma unroll
            for (int m = 0; m < 4; m++) {
                *(ulonglong2*)&g_z2[zb + m*64]     = make_ulonglong2(acc2[m][0], acc2[m][1]);
                *(ulonglong2*)&g_z2[zb + m*64 + 4] = make_ulonglong2(acc2[m][2], acc2[m][3]);
            }
            __syncthreads();                 // tmpT readers done before reuse as red
            float* redS = tmpT; float* redQ = tmpT + 2048;
            float s[8], qv[8];
            #pragma unroll
            for (int j = 0; j < 8; j++) { s[j]=0.f; qv[j]=0.f; }
            #pragma unroll
            for (int m = 0; m < 4; m++)
                #pragma unroll
                for (int q = 0; q < 4; q++) {
                    float2 f = ull2f2(acc2[m][q]);
                    s[2*q]   += f.x; qv[2*q]   += f.x*f.x;
                    s[2*q+1] += f.y; qv[2*q+1] += f.y*f.y;
                }
            #pragma unroll
            for (int j = 0; j < 8; j++) { redS[mg*64 + o8 + j] = s[j]; redQ[mg*64 + o8 + j] = qv[j]; }
            __syncthreads();
            if (tid < 128) {
                int pp = tid >> 6, h = tid & 63;
                float ss = 0.f, qq = 0.f;
                #pragma unroll 4
                for (int g = 0; g < 16; g++) { ss += redS[(pp*16+g)*64 + h]; qq += redQ[(pp*16+g)*64 + h]; }
                int bt = b*TT + t0 + pp;
                g_psum2[h*BT + bt] = ss; g_psq2[h*BT + bt] = qq;
            }
        }
    }
    __syncthreads();
    #pragma unroll
    for (int k = 0; k < 4; k++) {
        int i4 = 4*tid + k*1024;
        *(float4*)&g_S1p[(size_t)blk*VH + i4] = *(float4*)&S1a[i4];
    }
}

// ---------------- K4: S = S1 + sum_t relu(BN(z2)); E0/E1 -------------------
__global__ void __launch_bounds__(256) k_sumfinal() {
    int bv = blockIdx.x;                  // B*V
    int b = bv >> 6, v = bv & 63;
    int tid = threadIdx.x;
    int h = tid & 63, ph = tid >> 6;
    float a2 = g_a2[h], c2 = g_c2[h];
    size_t base = ((size_t)b*TT*VV + v)*HH + h;
    float s = 0.f, e0 = 0.f, e1 = 0.f;
    for (int t = ph; t < TT; t += 4) {
        float z = g_z2[base + (size_t)t*VH];
        float x2 = fmaxf(fmaf(z, a2, c2), 0.f);
        s += x2;
        if (t == 0)     e0 = x2;
        if (t == TT-1)  e1 = x2;
    }
    float s1 = 0.f;
    for (int cc = ph; cc < NCHUNK; cc += 4)
        s1 += g_S1p[((size_t)(b*NCHUNK + cc))*VH + v*64 + h];
    __shared__ float sr[4][64], s1r[4][64], se0[64], se1[64];
    sr[ph][h] = s; s1r[ph][h] = s1;
    if (ph == 0) se0[h] = e0;
    if (ph == 3) se1[h] = e1;
    __syncthreads();
    if (tid < 64) {
        float S = sr[0][tid]+sr[1][tid]+sr[2][tid]+sr[3][tid]
                + s1r[0][tid]+s1r[1][tid]+s1r[2][tid]+s1r[3][tid];
        int o = b*VH + v*HH + tid;
        g_S[o]  = S;
        g_E0[o] = se0[tid] + g_E0x1[o];
        g_E1[o] = se1[tid] + g_E1x1[o];
    }
}

// ---------------- K5: collapsed conv+mean -----------------------------------
__global__ void __launch_bounds__(256) k_pool(const float* __restrict__ tw,
                                              const float* __restrict__ tb) {
    int o = blockIdx.x;               // 256
    int tid = threadIdx.x;
    float acc[BB];
    #pragma unroll
    for (int b = 0; b < BB; b++) acc[b] = 0.f;
    const float* two = tw + (size_t)o*VH*3;
    for (int i = tid; i < VH; i += 256) {
        float t0 = two[i*3+0], t1 = two[i*3+1], t2 = two[i*3+2];
        float ts = t0 + t1 + t2;
        #pragma unroll
        for (int b = 0; b < BB; b++) {
            int ix = b*VH + i;
            acc[b] += ts*g_S[ix] - t0*g_E1[ix] - t2*g_E0[ix];
        }
    }
    __shared__ float red[256];
    float tbv = tb[o];
    #pragma unroll 1
    for (int b = 0; b < BB; b++) {
        red[tid] = acc[b];
        __syncthreads();
        for (int st = 128; st > 0; st >>= 1) {
            if (tid < st) red[tid] += red[tid+st];
            __syncthreads();
        }
        if (tid == 0) g_y[b*TC + o] = red[0]*(1.f/TT) + tbv;
        __syncthreads();
    }
}

// ---------------- K6: FC head ------------------------------------------------
__global__ void __launch_bounds__(256) k_fc(const float* __restrict__ f1w,
                                            const float* __restrict__ f1b,
                                            const float* __restrict__ f2w,
                                            const float* __restrict__ f2b,
                                            float* __restrict__ out) {
    __shared__ float ys[BB*TC];
    __shared__ float hs[BB*128];
    int tid = threadIdx.x;
    for (int i = tid; i < BB*TC; i += 256) ys[i] = g_y[i];
    __syncthreads();
    int b = tid >> 4, jq = (tid & 15) * 8;
    float acc[8];
    #pragma unroll
    for (int j = 0; j < 8; j++) acc[j] = f1b[jq+j];
    for (int o = 0; o < TC; o++) {
        float yv = ys[b*TC + o];
        const float* w = f1w + o*128 + jq;
        #pragma unroll
        for (int j = 0; j < 8; j++) acc[j] += yv * w[j];
    }
    #pragma unroll
    for (int j = 0; j < 8; j++) hs[b*128 + jq + j] = fmaxf(acc[j], 0.f);
    __syncthreads();
    if (tid < BB*10) {
        int bb = tid / 10, n = tid % 10;
        float s = f2b[n];
        #pragma unroll 8
        for (int j = 0; j < 128; j++) s += hs[bb*128 + j] * f2w[j*10 + n];
        out[tid] = s;
    }
}

// ---------------- launch ------------------------------------------------------
extern "C" void kernel_launch(void* const* d_in, const int* in_sizes, int n_in,
                              void* d_out, int out_size) {
    const float* x    = (const float*)d_in[0];
    const float* adj  = (const float*)d_in[1];
    const float* w1   = (const float*)d_in[2];
    const float* b1   = (const float*)d_in[3];
    const float* g1   = (const float*)d_in[4];
    const float* be1  = (const float*)d_in[5];
    const float* w2   = (const float*)d_in[6];
    const float* b2   = (const float*)d_in[7];
    const float* g2   = (const float*)d_in[8];
    const float* be2  = (const float*)d_in[9];
    const float* tw   = (const float*)d_in[10];
    const float* tb   = (const float*)d_in[11];
    const float* f1w  = (const float*)d_in[12];
    const float* f1b  = (const float*)d_in[13];
    const float* f2w  = (const float*)d_in[14];
    const float* f2b  = (const float*)d_in[15];
    float* out = (float*)d_out;

    cudaFuncSetAttribute(k_layer1, cudaFuncAttributeMaxDynamicSharedMemorySize, 53248);
    cudaFuncSetAttribute(k_layer2, cudaFuncAttributeMaxDynamicSharedMemorySize, 114688);

    k_adj<<<BB, 256>>>(adj);
    k_layer1<<<BB*NCHUNK, 256, 53248>>>(x, w1, b1);
    k_stats<<<HH, 256>>>(0, g1, be1);
    k_layer2<<<BB*NCHUNK, 256, 114688>>>(w2, b2);
    k_stats<<<HH, 256>>>(1, g2, be2);
    k_sumfinal<<<BB*VV, 256>>>();
    k_pool<<<TC, 256>>>(tw, tb);
    k_fc<<<1, 256>>>(f1w, f1b, f2w, f2b, out);
}

// round 6
// speedup vs baseline: 2.0129x; 1.4451x over previous
#include <cuda_runtime.h>
#include <cuda_bf16.h>
#include <cstdint>

#define BB 16
#define TT 512
#define VV 64
#define HH 64
#define BT (BB*TT)
#define VH (VV*HH)
#define TC 256

// ---------------- scratch ----------------------------------------------------
__device__ __nv_bfloat16 g_adjH[BB*4096], g_adjL[BB*4096]; // swizzled tiles [b][v][w]
__device__ __nv_bfloat16 g_w1H[1024],  g_w1L[1024];        // swizzled [c=16][h=64]
__device__ __nv_bfloat16 g_w2H[4096],  g_w2L[4096];        // swizzled [h][o]
__device__ float g_z1[(size_t)BT*VH];
__device__ float g_z2[(size_t)BT*VH];
__device__ float g_psum1[HH*BT], g_psq1[HH*BT];
__device__ float g_psum2[HH*BT], g_psq2[HH*BT];
__device__ float g_a1[HH], g_c1[HH], g_a2[HH], g_c2[HH];
__device__ float g_S[BB*VH], g_E0[BB*VH], g_E1[BB*VH];
__device__ float g_y[BB*TC];

extern __shared__ unsigned char s_dyn[];

// ---------------- helpers -----------------------------------------------------
// bf16 tile: 64-col rows, 128B pitch, XOR-swizzled 16B chunks
__device__ __forceinline__ uint32_t toff(int r, int cB) {
    return (uint32_t)(r*128 + (cB ^ ((r & 7) << 4)));
}
// fp32 stage tile: quad-granular XOR swizzle (float index)
__device__ __forceinline__ int zoff(int r, int c) {
    return r*64 + ((((c >> 2) ^ r) & 15) << 2) + (c & 3);
}
__device__ __forceinline__ void ldsm4(uint32_t* r, unsigned char* p) {
    uint32_t a; asm("{ .reg .u64 t; cvta.to.shared.u64 t, %1; cvt.u32.u64 %0, t; }" : "=r"(a) : "l"(p));
    asm volatile("ldmatrix.sync.aligned.m8n8.x4.shared.b16 {%0,%1,%2,%3}, [%4];"
        : "=r"(r[0]), "=r"(r[1]), "=r"(r[2]), "=r"(r[3]) : "r"(a));
}
__device__ __forceinline__ void ldsm2t(uint32_t& r0, uint32_t& r1, unsigned char* p) {
    uint32_t a; asm("{ .reg .u64 t; cvta.to.shared.u64 t, %1; cvt.u32.u64 %0, t; }" : "=r"(a) : "l"(p));
    asm volatile("ldmatrix.sync.aligned.m8n8.x2.trans.shared.b16 {%0,%1}, [%2];"
        : "=r"(r0), "=r"(r1) : "r"(a));
}
__device__ __forceinline__ void mmabf(float* c, const uint32_t* a, uint32_t b0, uint32_t b1) {
    asm volatile("mma.sync.aligned.m16n8k16.row.col.f32.bf16.bf16.f32 "
        "{%0,%1,%2,%3},{%4,%5,%6,%7},{%8,%9},{%0,%1,%2,%3};"
        : "+f"(c[0]), "+f"(c[1]), "+f"(c[2]), "+f"(c[3])
        : "r"(a[0]), "r"(a[1]), "r"(a[2]), "r"(a[3]), "r"(b0), "r"(b1));
}
// pack (f0 -> low, f1 -> high) bf16 hi word + residual word
__device__ __forceinline__ void split2(float f0, float f1, uint32_t& hi, uint32_t& lo) {
    asm("cvt.rn.bf16x2.f32 %0, %1, %2;" : "=r"(hi) : "f"(f1), "f"(f0));
    float h0 = __uint_as_float(hi << 16);
    float h1 = __uint_as_float(hi & 0xffff0000u);
    asm("cvt.rn.bf16x2.f32 %0, %1, %2;" : "=r"(lo) : "f"(f1 - h1), "f"(f0 - h0));
}
// A frags (16x16 at mt,kt) from 64-wide swizzled tile
__device__ __forceinline__ void lda(uint32_t* a, unsigned char* base, int mt, int kt, int lane) {
    int row = mt*16 + (lane & 7) + (lane & 8);
    int cB  = kt*32 + ((lane >> 4) << 4);
    ldsm4(a, base + toff(row, cB));
}
// B frags (16 rows x 8 cols at kt,nt), trans
__device__ __forceinline__ void ldb(uint32_t& b0, uint32_t& b1, unsigned char* base, int kt, int nt, int lane) {
    int row = kt*16 + (lane & 15);
    ldsm2t(b0, b1, base + toff(row, nt*16));
}

// ---------------- K0: prep ----------------------------------------------------
__global__ void k_prep(const float* __restrict__ adj, const float* __restrict__ w1,
                       const float* __restrict__ w2) {
    int b = blockIdx.x, tid = threadIdx.x;
    __shared__ float dis[64];
    const float* A = adj + b*4096;
    if (tid < 64) {
        float s = 0.f;
        #pragma unroll 8
        for (int w = 0; w < 64; w++) s += A[tid*64 + w];
        dis[tid] = rsqrtf(s + 1e-6f);
    }
    __syncthreads();
    for (int idx = tid; idx < 4096; idx += 256) {
        int v = idx >> 6, w = idx & 63;
        float a = dis[v] * A[idx] * dis[w];
        __nv_bfloat16 hb = __float2bfloat16(a);
        __nv_bfloat16 lb = __float2bfloat16(a - __bfloat162float(hb));
        uint32_t e = toff(v, w*2) >> 1;
        g_adjH[b*4096 + e] = hb; g_adjL[b*4096 + e] = lb;
    }
    if (b == 0) {
        for (int idx = tid; idx < 1024; idx += 256) {
            int c = idx >> 6, h = idx & 63;
            float val = w1[c*64 + h];
            __nv_bfloat16 hb = __float2bfloat16(val);
            __nv_bfloat16 lb = __float2bfloat16(val - __bfloat162float(hb));
            uint32_t e = toff(c, h*2) >> 1;
            g_w1H[e] = hb; g_w1L[e] = lb;
        }
        for (int idx = tid; idx < 4096; idx += 256) {
            int h = idx >> 6, o = idx & 63;
            float val = w2[h*64 + o];
            __nv_bfloat16 hb = __float2bfloat16(val);
            __nv_bfloat16 lb = __float2bfloat16(val - __bfloat162float(hb));
            uint32_t e = toff(h, o*2) >> 1;
            g_w2H[e] = hb; g_w2L[e] = lb;
        }
    }
}

// ---------------- shared epilogue: stage acc -> swizzled fp32, sums, store ----
__device__ __forceinline__ void epilogue(float acc[4][8][4], float* zs, int lane,
                                         float* zout, float* psum, float* psq, int bt) {
    #pragma unroll
    for (int mt = 0; mt < 4; mt++)
        #pragma unroll
        for (int nt = 0; nt < 8; nt++) {
            int r = mt*16 + (lane >> 2), c = nt*8 + (lane & 3)*2;
            *(float2*)&zs[zoff(r, c)]   = make_float2(acc[mt][nt][0], acc[mt][nt][1]);
            *(float2*)&zs[zoff(r+8, c)] = make_float2(acc[mt][nt][2], acc[mt][nt][3]);
        }
    __syncwarp();
    float s0 = 0.f, q0 = 0.f, s1 = 0.f, q1 = 0.f;
    #pragma unroll 8
    for (int r = 0; r < 64; r++) {
        float v0 = zs[zoff(r, lane)];
        float v1 = zs[zoff(r, lane + 32)];
        s0 += v0; q0 += v0*v0; s1 += v1; q1 += v1*v1;
    }
    psum[lane*BT + bt] = s0; psum[(lane+32)*BT + bt] = s1;
    psq[lane*BT + bt]  = q0; psq[(lane+32)*BT + bt]  = q1;
    #pragma unroll
    for (int it = 0; it < 32; it++) {
        int idx = it*32 + lane;
        int r = idx >> 4, cq = (idx & 15) << 2;
        *(float4*)&zout[r*64 + cq] = *(float4*)&zs[zoff(r, cq)];
    }
}

// ---------------- K1: layer1 HMMA ----------------------------------------------
// smem: ADJH 0(8K) ADJL 8K | W1H 16K(2K) W1L 18K(2K) | warp regions at 20480
#define L1_WREG 20480
#define L1_SM   (20480 + 4*16384)
__global__ void __launch_bounds__(128, 2) k_l1(const float* __restrict__ x) {
    int blk = blockIdx.x, b = blk >> 7, chunk = blk & 127;
    int tid = threadIdx.x, lane = tid & 31, wq = tid >> 5;
    unsigned char* sm = s_dyn;
    {
        const uint4* s1 = (const uint4*)(g_adjH + b*4096);
        const uint4* s2 = (const uint4*)(g_adjL + b*4096);
        uint4* d1 = (uint4*)sm; uint4* d2 = (uint4*)(sm + 8192);
        for (int i = tid; i < 512; i += 128) { d1[i] = s1[i]; d2[i] = s2[i]; }
        const uint4* s3 = (const uint4*)g_w1H; const uint4* s4 = (const uint4*)g_w1L;
        uint4* d3 = (uint4*)(sm + 16384); uint4* d4 = (uint4*)(sm + 18432);
        if (tid < 128) { d3[tid] = s3[tid]; d4[tid] = s4[tid]; }
    }
    __syncthreads();

    int t = chunk*4 + wq;
    int bt = b*TT + t;
    unsigned char* XH = sm + L1_WREG + wq*16384;
    unsigned char* XL = XH + 8192;
    unsigned char* AH = sm; unsigned char* AL = sm + 8192;
    unsigned char* WH = sm + 16384; unsigned char* WL = sm + 18432;

    // build X tile [w=64][c=16] bf16 hi/lo
    const float* xg = x + (size_t)bt*1024;
    #pragma unroll
    for (int it = 0; it < 8; it++) {
        int idx = it*32 + lane;             // 256 quad-groups
        int r = idx >> 2, cq = (idx & 3) << 2;
        float4 u = *(const float4*)&xg[r*16 + cq];
        uint32_t h01, l01, h23, l23;
        split2(u.x, u.y, h01, l01); split2(u.z, u.w, h23, l23);
        uint32_t off = toff(r, cq*2);
        *(uint2*)(XH + off) = make_uint2(h01, h23);
        *(uint2*)(XL + off) = make_uint2(l01, l23);
    }
    __syncwarp();

    // GEMM1': tmp[v][c] = sum_w A[v][w] X[w][c]   (m 4 tiles, n 2 tiles, k 4)
    float acc1[4][2][4];
    #pragma unroll
    for (int m = 0; m < 4; m++)
        #pragma unroll
        for (int n = 0; n < 2; n++) { acc1[m][n][0]=0; acc1[m][n][1]=0; acc1[m][n][2]=0; acc1[m][n][3]=0; }
    #pragma unroll
    for (int kt = 0; kt < 4; kt++) {
        uint32_t aH[4][4], aL[4][4];
        #pragma unroll
        for (int mt = 0; mt < 4; mt++) { lda(aH[mt], AH, mt, kt, lane); lda(aL[mt], AL, mt, kt, lane); }
        #pragma unroll
        for (int nt = 0; nt < 2; nt++) {
            uint32_t bh0, bh1, bl0, bl1;
            ldb(bh0, bh1, XH, kt, nt, lane);
            ldb(bl0, bl1, XL, kt, nt, lane);
            #pragma unroll
            for (int mt = 0; mt < 4; mt++) {
                mmabf(acc1[mt][nt], aH[mt], bh0, bh1);
                mmabf(acc1[mt][nt], aL[mt], bh0, bh1);
                mmabf(acc1[mt][nt], aH[mt], bl0, bl1);
            }
        }
    }
    __syncwarp();
    // store tmp hi/lo into X region (cols 0..15)
    #pragma unroll
    for (int mt = 0; mt < 4; mt++)
        #pragma unroll
        for (int nt = 0; nt < 2; nt++) {
            int r = mt*16 + (lane >> 2), cB = (nt*8 + (lane & 3)*2)*2;
            uint32_t h, l;
            split2(acc1[mt][nt][0], acc1[mt][nt][1], h, l);
            *(uint32_t*)(XH + toff(r, cB)) = h; *(uint32_t*)(XL + toff(r, cB)) = l;
            split2(acc1[mt][nt][2], acc1[mt][nt][3], h, l);
            *(uint32_t*)(XH + toff(r+8, cB)) = h; *(uint32_t*)(XL + toff(r+8, cB)) = l;
        }
    __syncwarp();

    // GEMM2': z1[v][h] = sum_c tmp[v][c] W1[c][h]   (k = 1 tile)
    float acc2[4][8][4];
    #pragma unroll
    for (int m = 0; m < 4; m++)
        #pragma unroll
        for (int n = 0; n < 8; n++) { acc2[m][n][0]=0; acc2[m][n][1]=0; acc2[m][n][2]=0; acc2[m][n][3]=0; }
    {
        uint32_t aH[4][4], aL[4][4];
        #pragma unroll
        for (int mt = 0; mt < 4; mt++) { lda(aH[mt], XH, mt, 0, lane); lda(aL[mt], XL, mt, 0, lane); }
        #pragma unroll
        for (int nt = 0; nt < 8; nt++) {
            uint32_t bh0, bh1, bl0, bl1;
            ldb(bh0, bh1, WH, 0, nt, lane);
            ldb(bl0, bl1, WL, 0, nt, lane);
            #pragma unroll
            for (int mt = 0; mt < 4; mt++) {
                mmabf(acc2[mt][nt], aH[mt], bh0, bh1);
                mmabf(acc2[mt][nt], aL[mt], bh0, bh1);
                mmabf(acc2[mt][nt], aH[mt], bl0, bl1);
            }
        }
    }
    __syncwarp();
    epilogue(acc2, (float*)XH, lane, g_z1 + (size_t)bt*4096, g_psum1, g_psq1, bt);
}

// ---------------- K2: finalize BN affine ---------------------------------------
__global__ void k_stats(int layer, const float* __restrict__ g, const float* __restrict__ be) {
    int h = blockIdx.x, tid = threadIdx.x;
    const float* ps = layer ? g_psum2 : g_psum1;
    const float* pq = layer ? g_psq2  : g_psq1;
    __shared__ float ss[256], sq[256];
    float s = 0.f, q = 0.f;
    for (int i = tid; i < BT; i += 256) { s += ps[h*BT + i]; q += pq[h*BT + i]; }
    ss[tid] = s; sq[tid] = q;
    __syncthreads();
    for (int st = 128; st > 0; st >>= 1) {
        if (tid < st) { ss[tid] += ss[tid+st]; sq[tid] += sq[tid+st]; }
        __syncthreads();
    }
    if (tid == 0) {
        const float N = (float)(BT*VV);
        float mean = ss[0] / N;
        float var  = sq[0] / N - mean*mean;
        float av = g[h] * rsqrtf(var + 1e-5f);
        if (layer) { g_a2[h] = av; g_c2[h] = be[h] - mean*av; }
        else       { g_a1[h] = av; g_c1[h] = be[h] - mean*av; }
    }
}

// ---------------- K3: layer2 HMMA ----------------------------------------------
// smem: ADJH 0(8K) ADJL 8K | W2H 16K(8K) W2L 24K(8K) | a1/c1 32768(512B) | wreg 33280
#define L2_WREG 33280
#define L2_SM   (33280 + 4*16384)
__global__ void __launch_bounds__(128, 2) k_l2() {
    int blk = blockIdx.x, b = blk >> 7, chunk = blk & 127;
    int tid = threadIdx.x, lane = tid & 31, wq = tid >> 5;
    unsigned char* sm = s_dyn;
    float* a1s = (float*)(sm + 32768);
    float* c1s = a1s + 64;
    {
        const uint4* s1 = (const uint4*)(g_adjH + b*4096);
        const uint4* s2 = (const uint4*)(g_adjL + b*4096);
        uint4* d1 = (uint4*)sm; uint4* d2 = (uint4*)(sm + 8192);
        for (int i = tid; i < 512; i += 128) { d1[i] = s1[i]; d2[i] = s2[i]; }
        const uint4* s3 = (const uint4*)g_w2H; const uint4* s4 = (const uint4*)g_w2L;
        uint4* d3 = (uint4*)(sm + 16384); uint4* d4 = (uint4*)(sm + 24576);
        for (int i = tid; i < 512; i += 128) { d3[i] = s3[i]; d4[i] = s4[i]; }
        if (tid < 64) { a1s[tid] = g_a1[tid]; c1s[tid] = g_c1[tid]; }
    }
    __syncthreads();

    int t = chunk*4 + wq;
    int bt = b*TT + t;
    unsigned char* XH = sm + L2_WREG + wq*16384;
    unsigned char* XL = XH + 8192;
    unsigned char* AH = sm; unsigned char* AL = sm + 8192;
    unsigned char* WH = sm + 16384; unsigned char* WL = sm + 24576;

    // build x1 tile [w=64][h=64] = relu(a1*z1+c1), bf16 hi/lo
    const float* zt = g_z1 + (size_t)bt*4096;
    #pragma unroll
    for (int it = 0; it < 32; it++) {
        int idx = it*32 + lane;
        int r = idx >> 4, cq = (idx & 15) << 2;
        float4 u = *(const float4*)&zt[r*64 + cq];
        float4 av = *(float4*)&a1s[cq];
        float4 cv = *(float4*)&c1s[cq];
        float e0 = fmaxf(fmaf(u.x, av.x, cv.x), 0.f);
        float e1 = fmaxf(fmaf(u.y, av.y, cv.y), 0.f);
        float e2 = fmaxf(fmaf(u.z, av.z, cv.z), 0.f);
        float e3 = fmaxf(fmaf(u.w, av.w, cv.w), 0.f);
        uint32_t h01, l01, h23, l23;
        split2(e0, e1, h01, l01); split2(e2, e3, h23, l23);
        uint32_t off = toff(r, cq*2);
        *(uint2*)(XH + off) = make_uint2(h01, h23);
        *(uint2*)(XL + off) = make_uint2(l01, l23);
    }
    __syncwarp();

    float acc[4][8][4];
    #pragma unroll
    for (int m = 0; m < 4; m++)
        #pragma unroll
        for (int n = 0; n < 8; n++) { acc[m][n][0]=0; acc[m][n][1]=0; acc[m][n][2]=0; acc[m][n][3]=0; }

    // GEMM1: tmp[v][h] = sum_w A[v][w] x1[w][h]
    #pragma unroll
    for (int kt = 0; kt < 4; kt++) {
        uint32_t aH[4][4], aL[4][4];
        #pragma unroll
        for (int mt = 0; mt < 4; mt++) { lda(aH[mt], AH, mt, kt, lane); lda(aL[mt], AL, mt, kt, lane); }
        #pragma unroll
        for (int nt = 0; nt < 8; nt++) {
            uint32_t bh0, bh1, bl0, bl1;
            ldb(bh0, bh1, XH, kt, nt, lane);
            ldb(bl0, bl1, XL, kt, nt, lane);
            #pragma unroll
            for (int mt = 0; mt < 4; mt++) {
                mmabf(acc[mt][nt], aH[mt], bh0, bh1);
                mmabf(acc[mt][nt], aL[mt], bh0, bh1);
                mmabf(acc[mt][nt], aH[mt], bl0, bl1);
            }
        }
    }
    __syncwarp();
    // store tmp hi/lo over X region
    #pragma unroll
    for (int mt = 0; mt < 4; mt++)
        #pragma unroll
        for (int nt = 0; nt < 8; nt++) {
            int r = mt*16 + (lane >> 2), cB = (nt*8 + (lane & 3)*2)*2;
            uint32_t h, l;
            split2(acc[mt][nt][0], acc[mt][nt][1], h, l);
            *(uint32_t*)(XH + toff(r, cB)) = h; *(uint32_t*)(XL + toff(r, cB)) = l;
            split2(acc[mt][nt][2], acc[mt][nt][3], h, l);
            *(uint32_t*)(XH + toff(r+8, cB)) = h; *(uint32_t*)(XL + toff(r+8, cB)) = l;
        }
    __syncwarp();

    // GEMM2: z2[v][o] = sum_h tmp[v][h] W2[h][o]
    #pragma unroll
    for (int m = 0; m < 4; m++)
        #pragma unroll
        for (int n = 0; n < 8; n++) { acc[m][n][0]=0; acc[m][n][1]=0; acc[m][n][2]=0; acc[m][n][3]=0; }
    #pragma unroll
    for (int kt = 0; kt < 4; kt++) {
        uint32_t aH[4][4], aL[4][4];
        #pragma unroll
        for (int mt = 0; mt < 4; mt++) { lda(aH[mt], XH, mt, kt, lane); lda(aL[mt], XL, mt, kt, lane); }
        #pragma unroll
        for (int nt = 0; nt < 8; nt++) {
            uint32_t bh0, bh1, bl0, bl1;
            ldb(bh0, bh1, WH, kt, nt, lane);
            ldb(bl0, bl1, WL, kt, nt, lane);
            #pragma unroll
            for (int mt = 0; mt < 4; mt++) {
                mmabf(acc[mt][nt], aH[mt], bh0, bh1);
                mmabf(acc[mt][nt], aL[mt], bh0, bh1);
                mmabf(acc[mt][nt], aH[mt], bl0, bl1);
            }
        }
    }
    __syncwarp();
    epilogue(acc, (float*)XH, lane, g_z2 + (size_t)bt*4096, g_psum2, g_psq2, bt);
}

// ---------------- K4: x = relu(BN(z1)) + relu(BN(z2)); reduce over T ----------
__global__ void __launch_bounds__(256) k_sumfinal() {
    int bv = blockIdx.x;
    int b = bv >> 6, v = bv & 63;
    int tid = threadIdx.x;
    int h = tid & 63, ph = tid >> 6;
    float a1 = g_a1[h], c1 = g_c1[h], a2 = g_a2[h], c2 = g_c2[h];
    size_t base = ((size_t)b*TT*VV + v)*HH + h;
    float s = 0.f, e0 = 0.f, e1 = 0.f;
    for (int t = ph; t < TT; t += 4) {
        size_t ix = base + (size_t)t*VH;
        float z1v = g_z1[ix], z2v = g_z2[ix];
        float xv = fmaxf(fmaf(z1v, a1, c1), 0.f) + fmaxf(fmaf(z2v, a2, c2), 0.f);
        s += xv;
        if (t == 0)    e0 = xv;
        if (t == TT-1) e1 = xv;
    }
    __shared__ float sr[4][64], se0[64], se1[64];
    sr[ph][h] = s;
    if (ph == 0) se0[h] = e0;
    if (ph == 3) se1[h] = e1;
    __syncthreads();
    if (tid < 64) {
        int o = b*VH + v*HH + tid;
        g_S[o]  = sr[0][tid] + sr[1][tid] + sr[2][tid] + sr[3][tid];
        g_E0[o] = se0[tid]; g_E1[o] = se1[tid];
    }
}

// ---------------- K5: collapsed conv+mean --------------------------------------
__global__ void __launch_bounds__(256) k_pool(const float* __restrict__ tw,
                                              const float* __restrict__ tb) {
    int o = blockIdx.x, tid = threadIdx.x;
    float acc[BB];
    #pragma unroll
    for (int b = 0; b < BB; b++) acc[b] = 0.f;
    const float* two = tw + (size_t)o*VH*3;
    for (int i = tid; i < VH; i += 256) {
        float t0 = two[i*3+0], t1 = two[i*3+1], t2 = two[i*3+2];
        float ts = t0 + t1 + t2;
        #pragma unroll
        for (int b = 0; b < BB; b++) {
            int ix = b*VH + i;
            acc[b] += ts*g_S[ix] - t0*g_E1[ix] - t2*g_E0[ix];
        }
    }
    __shared__ float red[256];
    float tbv = tb[o];
    #pragma unroll 1
    for (int b = 0; b < BB; b++) {
        red[tid] = acc[b];
        __syncthreads();
        for (int st = 128; st > 0; st >>= 1) {
            if (tid < st) red[tid] += red[tid+st];
            __syncthreads();
        }
        if (tid == 0) g_y[b*TC + o] = red[0]*(1.f/TT) + tbv;
        __syncthreads();
    }
}

// ---------------- K6: FC head ---------------------------------------------------
__global__ void __launch_bounds__(256) k_fc(const float* __restrict__ f1w,
                                            const float* __restrict__ f1b,
                                            const float* __restrict__ f2w,
                                            const float* __restrict__ f2b,
                                            float* __restrict__ out) {
    __shared__ float ys[BB*TC];
    __shared__ float hs[BB*128];
    int tid = threadIdx.x;
    for (int i = tid; i < BB*TC; i += 256) ys[i] = g_y[i];
    __syncthreads();
    int b = tid >> 4, jq = (tid & 15) * 8;
    float acc[8];
    #pragma unroll
    for (int j = 0; j < 8; j++) acc[j] = f1b[jq+j];
    for (int o = 0; o < TC; o++) {
        float yv = ys[b*TC + o];
        const float* w = f1w + o*128 + jq;
        #pragma unroll
        for (int j = 0; j < 8; j++) acc[j] += yv * w[j];
    }
    #pragma unroll
    for (int j = 0; j < 8; j++) hs[b*128 + jq + j] = fmaxf(acc[j], 0.f);
    __syncthreads();
    if (tid < BB*10) {
        int bb = tid / 10, n = tid % 10;
        float s = f2b[n];
        #pragma unroll 8
        for (int j = 0; j < 128; j++) s += hs[bb*128 + j] * f2w[j*10 + n];
        out[tid] = s;
    }
}

// ---------------- launch ---------------------------------------------------------
extern "C" void kernel_launch(void* const* d_in, const int* in_sizes, int n_in,
                              void* d_out, int out_size) {
    const float* x    = (const float*)d_in[0];
    const float* adj  = (const float*)d_in[1];
    const float* w1   = (const float*)d_in[2];
    const float* g1   = (const float*)d_in[4];
    const float* be1  = (const float*)d_in[5];
    const float* w2   = (const float*)d_in[6];
    const float* g2   = (const float*)d_in[8];
    const float* be2  = (const float*)d_in[9];
    const float* tw   = (const float*)d_in[10];
    const float* tb   = (const float*)d_in[11];
    const float* f1w  = (const float*)d_in[12];
    const float* f1b  = (const float*)d_in[13];
    const float* f2w  = (const float*)d_in[14];
    const float* f2b  = (const float*)d_in[15];
    float* out = (float*)d_out;

    cudaFuncSetAttribute(k_l1, cudaFuncAttributeMaxDynamicSharedMemorySize, L1_SM);
    cudaFuncSetAttribute(k_l2, cudaFuncAttributeMaxDynamicSharedMemorySize, L2_SM);

    k_prep<<<BB, 256>>>(adj, w1, w2);
    k_l1<<<BB*128, 128, L1_SM>>>(x);
    k_stats<<<HH, 256>>>(0, g1, be1);
    k_l2<<<BB*128, 128, L2_SM>>>();
    k_stats<<<HH, 256>>>(1, g2, be2);
    k_sumfinal<<<BB*VV, 256>>>();
    k_pool<<<TC, 256>>>(tw, tb);
    k_fc<<<1, 256>>>(f1w, f1b, f2w, f2b, out);
}